// round 1
// baseline (speedup 1.0000x reference)
#include <cuda_runtime.h>
#include <cstdint>

static constexpr int D = 128;       // feature dim == hidden dim
static constexpr int MAXN = 100000; // nodes

// scratch accumulator: (1+eps)*x + scattered messages
__device__ float g_acc[(size_t)MAXN * D];

// ---------------------------------------------------------------------------
// Kernel 1: acc = (1 + eps) * x        (vectorized float4)
// ---------------------------------------------------------------------------
__global__ void init_kernel(const float* __restrict__ x,
                            const float* __restrict__ eps, int n4) {
    int i = blockIdx.x * blockDim.x + threadIdx.x;
    if (i >= n4) return;
    float s = 1.0f + *eps;
    float4 v = reinterpret_cast<const float4*>(x)[i];
    v.x *= s; v.y *= s; v.z *= s; v.w *= s;
    reinterpret_cast<float4*>(g_acc)[i] = v;
}

// ---------------------------------------------------------------------------
// Kernel 2: one warp per edge.
//   acc[u] += relu(x[v] + ea[e]);  acc[v] += relu(x[u] + ea[e])
// Each lane handles 4 floats (float4) -> 32 lanes cover D=128.
// Vector reductions (red.global.add.v4.f32) cut atomic ops 4x.
// ---------------------------------------------------------------------------
__global__ void scatter_kernel(const float* __restrict__ x,
                               const float* __restrict__ ea,
                               const int* __restrict__ ei, int E) {
    int gtid = blockIdx.x * blockDim.x + threadIdx.x;
    int e = gtid >> 5;
    int lane = gtid & 31;
    if (e >= E) return;

    int u = ei[e];
    int v = ei[E + e];

    float4 a  = reinterpret_cast<const float4*>(ea + (size_t)e * D)[lane];
    float4 xu = reinterpret_cast<const float4*>(x + (size_t)u * D)[lane];
    float4 xv = reinterpret_cast<const float4*>(x + (size_t)v * D)[lane];

    float4 mu, mv;
    mu.x = fmaxf(xv.x + a.x, 0.0f);
    mu.y = fmaxf(xv.y + a.y, 0.0f);
    mu.z = fmaxf(xv.z + a.z, 0.0f);
    mu.w = fmaxf(xv.w + a.w, 0.0f);
    mv.x = fmaxf(xu.x + a.x, 0.0f);
    mv.y = fmaxf(xu.y + a.y, 0.0f);
    mv.z = fmaxf(xu.z + a.z, 0.0f);
    mv.w = fmaxf(xu.w + a.w, 0.0f);

    float* pu = g_acc + (size_t)u * D + lane * 4;
    float* pv = g_acc + (size_t)v * D + lane * 4;
    asm volatile("red.global.add.v4.f32 [%0], {%1,%2,%3,%4};"
                 :: "l"(pu), "f"(mu.x), "f"(mu.y), "f"(mu.z), "f"(mu.w)
                 : "memory");
    asm volatile("red.global.add.v4.f32 [%0], {%1,%2,%3,%4};"
                 :: "l"(pv), "f"(mv.x), "f"(mv.y), "f"(mv.z), "f"(mv.w)
                 : "memory");
}

// ---------------------------------------------------------------------------
// Kernel 3: fused MLP.  out = relu(acc @ W1 + b1) @ W2 + b2
// Block: 256 threads, 64 rows/block. W1, W2 resident in SMEM.
// Thread (tx in [0,32), ty in [0,8)) computes an 8-row x 4-col register tile.
// Hidden tile is written back into the A-tile SMEM (reused) between phases.
// SMEM: 64*128*4 + 2*128*128*4 = 160 KB dynamic.
// ---------------------------------------------------------------------------
__global__ void __launch_bounds__(256, 1)
mlp_kernel(const float* __restrict__ W1, const float* __restrict__ b1,
           const float* __restrict__ W2, const float* __restrict__ b2,
           float* __restrict__ out, int N) {
    extern __shared__ float sm[];
    float* As  = sm;                  // 64 x 128  (A tile, then hidden tile)
    float* W1s = sm + 64 * 128;       // 128 x 128
    float* W2s = W1s + 128 * 128;     // 128 x 128

    int tid = threadIdx.x;
    int tx = tid & 31;
    int ty = tid >> 5;
    int row0 = blockIdx.x * 64;

    // stage weights + A tile
    {
        const float4* W1g = reinterpret_cast<const float4*>(W1);
        const float4* W2g = reinterpret_cast<const float4*>(W2);
        float4* W1s4 = reinterpret_cast<float4*>(W1s);
        float4* W2s4 = reinterpret_cast<float4*>(W2s);
        #pragma unroll
        for (int i = tid; i < 128 * 128 / 4; i += 256) {
            W1s4[i] = W1g[i];
            W2s4[i] = W2g[i];
        }
        float4* As4 = reinterpret_cast<float4*>(As);
        #pragma unroll
        for (int i = tid; i < 64 * 128 / 4; i += 256) {
            int r = i >> 5;
            int gr = row0 + r;
            As4[i] = (gr < N)
                ? reinterpret_cast<const float4*>(g_acc + (size_t)gr * D)[i & 31]
                : make_float4(0.f, 0.f, 0.f, 0.f);
        }
    }
    __syncthreads();

    float acc[8][4];
    #pragma unroll
    for (int i = 0; i < 8; i++)
        acc[i][0] = acc[i][1] = acc[i][2] = acc[i][3] = 0.f;

    // ---- phase 1: hidden = relu(A @ W1 + b1) ----
    {
        const float4* As4 = reinterpret_cast<const float4*>(As);
        const float4* Ws4 = reinterpret_cast<const float4*>(W1s);
        for (int k4 = 0; k4 < 32; k4++) {
            float4 a4[8];
            #pragma unroll
            for (int i = 0; i < 8; i++) a4[i] = As4[(ty * 8 + i) * 32 + k4];
            #pragma unroll
            for (int kk = 0; kk < 4; kk++) {
                float4 w = Ws4[(k4 * 4 + kk) * 32 + tx];
                #pragma unroll
                for (int i = 0; i < 8; i++) {
                    float a = reinterpret_cast<const float*>(&a4[i])[kk];
                    acc[i][0] = fmaf(a, w.x, acc[i][0]);
                    acc[i][1] = fmaf(a, w.y, acc[i][1]);
                    acc[i][2] = fmaf(a, w.z, acc[i][2]);
                    acc[i][3] = fmaf(a, w.w, acc[i][3]);
                }
            }
        }
    }

    float4 bias1 = reinterpret_cast<const float4*>(b1)[tx];
    __syncthreads();   // all phase-1 reads of As complete before overwrite
    {
        float4* As4 = reinterpret_cast<float4*>(As);
        #pragma unroll
        for (int i = 0; i < 8; i++) {
            float4 h;
            h.x = fmaxf(acc[i][0] + bias1.x, 0.f);
            h.y = fmaxf(acc[i][1] + bias1.y, 0.f);
            h.z = fmaxf(acc[i][2] + bias1.z, 0.f);
            h.w = fmaxf(acc[i][3] + bias1.w, 0.f);
            As4[(ty * 8 + i) * 32 + tx] = h;
        }
    }
    __syncthreads();

    #pragma unroll
    for (int i = 0; i < 8; i++)
        acc[i][0] = acc[i][1] = acc[i][2] = acc[i][3] = 0.f;

    // ---- phase 2: out = hidden @ W2 + b2 ----
    {
        const float4* Hs4 = reinterpret_cast<const float4*>(As);
        const float4* Ws4 = reinterpret_cast<const float4*>(W2s);
        for (int k4 = 0; k4 < 32; k4++) {
            float4 a4[8];
            #pragma unroll
            for (int i = 0; i < 8; i++) a4[i] = Hs4[(ty * 8 + i) * 32 + k4];
            #pragma unroll
            for (int kk = 0; kk < 4; kk++) {
                float4 w = Ws4[(k4 * 4 + kk) * 32 + tx];
                #pragma unroll
                for (int i = 0; i < 8; i++) {
                    float a = reinterpret_cast<const float*>(&a4[i])[kk];
                    acc[i][0] = fmaf(a, w.x, acc[i][0]);
                    acc[i][1] = fmaf(a, w.y, acc[i][1]);
                    acc[i][2] = fmaf(a, w.z, acc[i][2]);
                    acc[i][3] = fmaf(a, w.w, acc[i][3]);
                }
            }
        }
    }

    float4 bias2 = reinterpret_cast<const float4*>(b2)[tx];
    #pragma unroll
    for (int i = 0; i < 8; i++) {
        int gr = row0 + ty * 8 + i;
        if (gr < N) {
            float4 o;
            o.x = acc[i][0] + bias2.x;
            o.y = acc[i][1] + bias2.y;
            o.z = acc[i][2] + bias2.z;
            o.w = acc[i][3] + bias2.w;
            reinterpret_cast<float4*>(out)[(size_t)gr * 32 + tx] = o;
        }
    }
}

// ---------------------------------------------------------------------------
// Launch. Input order (metadata): x, edge_attr, W1, b1, W2, b2, eps_node,
// edge_index. Output: [N, 128] float32.
// ---------------------------------------------------------------------------
extern "C" void kernel_launch(void* const* d_in, const int* in_sizes, int n_in,
                              void* d_out, int out_size) {
    const float* x   = (const float*)d_in[0];
    const float* ea  = (const float*)d_in[1];
    const float* W1  = (const float*)d_in[2];
    const float* b1  = (const float*)d_in[3];
    const float* W2  = (const float*)d_in[4];
    const float* b2  = (const float*)d_in[5];
    const float* eps = (const float*)d_in[6];
    const int*   ei  = (const int*)d_in[7];

    int N = in_sizes[0] / D;
    int E = in_sizes[1] / D;

    constexpr int MLP_SMEM = (64 * 128 + 2 * 128 * 128) * 4;  // 160 KB
    cudaFuncSetAttribute(mlp_kernel,
                         cudaFuncAttributeMaxDynamicSharedMemorySize, MLP_SMEM);

    int n4 = N * D / 4;
    init_kernel<<<(n4 + 255) / 256, 256>>>(x, eps, n4);

    long long scatter_threads = (long long)E * 32;
    scatter_kernel<<<(int)((scatter_threads + 255) / 256), 256>>>(x, ea, ei, E);

    mlp_kernel<<<(N + 63) / 64, 256, MLP_SMEM>>>(W1, b1, W2, b2,
                                                 (float*)d_out, N);
}

// round 3
// speedup vs baseline: 1.3182x; 1.3182x over previous
#include <cuda_runtime.h>
#include <cuda_bf16.h>
#include <cstdint>

static constexpr int D = 128;       // feature dim == hidden dim
static constexpr int MAXN = 100000;

// accumulator: (1+eps)*x + scattered messages
__device__ float g_acc[(size_t)MAXN * D];
// pre-split, transposed bf16 weights: [n][k] row-major, 128x128 each
__device__ __align__(16) __nv_bfloat16 g_w1hi[16384];
__device__ __align__(16) __nv_bfloat16 g_w1lo[16384];
__device__ __align__(16) __nv_bfloat16 g_w2hi[16384];
__device__ __align__(16) __nv_bfloat16 g_w2lo[16384];

// ---------------------------------------------------------------------------
// helpers
// ---------------------------------------------------------------------------
__device__ __forceinline__ uint32_t smem_to_u32(const void* p) {
    uint32_t a;
    asm("{ .reg .u64 t; cvta.to.shared.u64 t, %1; cvt.u32.u64 %0, t; }"
        : "=r"(a) : "l"(p));
    return a;
}
__device__ __forceinline__ void ldsm4(uint32_t r[4], uint32_t addr) {
    asm volatile("ldmatrix.sync.aligned.m8n8.x4.shared.b16 {%0,%1,%2,%3}, [%4];"
                 : "=r"(r[0]), "=r"(r[1]), "=r"(r[2]), "=r"(r[3]) : "r"(addr));
}
__device__ __forceinline__ void mma16816(float c[4], const uint32_t a[4],
                                         uint32_t b0, uint32_t b1) {
    asm volatile("mma.sync.aligned.m16n8k16.row.col.f32.bf16.bf16.f32 "
                 "{%0,%1,%2,%3}, {%4,%5,%6,%7}, {%8,%9}, {%0,%1,%2,%3};"
                 : "+f"(c[0]), "+f"(c[1]), "+f"(c[2]), "+f"(c[3])
                 : "r"(a[0]), "r"(a[1]), "r"(a[2]), "r"(a[3]),
                   "r"(b0), "r"(b1));
}
// split two floats into packed bf16x2 hi + lo words
__device__ __forceinline__ void split2(float v0, float v1,
                                       uint32_t& hp, uint32_t& lp) {
    __nv_bfloat16 h0 = __float2bfloat16(v0);
    __nv_bfloat16 h1 = __float2bfloat16(v1);
    __nv_bfloat16 l0 = __float2bfloat16(v0 - __bfloat162float(h0));
    __nv_bfloat16 l1 = __float2bfloat16(v1 - __bfloat162float(h1));
    hp = (uint32_t)__bfloat16_as_ushort(h0) |
         ((uint32_t)__bfloat16_as_ushort(h1) << 16);
    lp = (uint32_t)__bfloat16_as_ushort(l0) |
         ((uint32_t)__bfloat16_as_ushort(l1) << 16);
}

// ---------------------------------------------------------------------------
// init: acc = (1+eps)*x
// ---------------------------------------------------------------------------
__global__ void init_kernel(const float* __restrict__ x,
                            const float* __restrict__ eps, int n4) {
    int i = blockIdx.x * blockDim.x + threadIdx.x;
    if (i >= n4) return;
    float s = 1.0f + *eps;
    float4 v = reinterpret_cast<const float4*>(x)[i];
    v.x *= s; v.y *= s; v.z *= s; v.w *= s;
    reinterpret_cast<float4*>(g_acc)[i] = v;
}

// ---------------------------------------------------------------------------
// weight prep: W [k][n] f32 -> hi/lo bf16 at [n][k]
// ---------------------------------------------------------------------------
__global__ void prep_kernel(const float* __restrict__ W1,
                            const float* __restrict__ W2) {
    int idx = blockIdx.x * blockDim.x + threadIdx.x;  // 0..32767
    int m = idx >> 14;
    int r = idx & 16383;
    int k = r >> 7, n = r & 127;
    float w = (m ? W2 : W1)[k * 128 + n];
    __nv_bfloat16 h = __float2bfloat16(w);
    __nv_bfloat16 l = __float2bfloat16(w - __bfloat162float(h));
    int e = n * 128 + k;
    if (m) { g_w2hi[e] = h; g_w2lo[e] = l; }
    else   { g_w1hi[e] = h; g_w1lo[e] = l; }
}

// ---------------------------------------------------------------------------
// scatter: one warp per edge, red.global.add.v4.f32
// ---------------------------------------------------------------------------
__global__ void scatter_kernel(const float* __restrict__ x,
                               const float* __restrict__ ea,
                               const int* __restrict__ ei, int E) {
    int gtid = blockIdx.x * blockDim.x + threadIdx.x;
    int e = gtid >> 5;
    int lane = gtid & 31;
    if (e >= E) return;

    int u = ei[e];
    int v = ei[E + e];

    float4 a  = reinterpret_cast<const float4*>(ea + (size_t)e * D)[lane];
    float4 xu = reinterpret_cast<const float4*>(x + (size_t)u * D)[lane];
    float4 xv = reinterpret_cast<const float4*>(x + (size_t)v * D)[lane];

    float4 mu, mv;
    mu.x = fmaxf(xv.x + a.x, 0.0f); mu.y = fmaxf(xv.y + a.y, 0.0f);
    mu.z = fmaxf(xv.z + a.z, 0.0f); mu.w = fmaxf(xv.w + a.w, 0.0f);
    mv.x = fmaxf(xu.x + a.x, 0.0f); mv.y = fmaxf(xu.y + a.y, 0.0f);
    mv.z = fmaxf(xu.z + a.z, 0.0f); mv.w = fmaxf(xu.w + a.w, 0.0f);

    float* pu = g_acc + (size_t)u * D + lane * 4;
    float* pv = g_acc + (size_t)v * D + lane * 4;
    asm volatile("red.global.add.v4.f32 [%0], {%1,%2,%3,%4};"
                 :: "l"(pu), "f"(mu.x), "f"(mu.y), "f"(mu.z), "f"(mu.w) : "memory");
    asm volatile("red.global.add.v4.f32 [%0], {%1,%2,%3,%4};"
                 :: "l"(pv), "f"(mv.x), "f"(mv.y), "f"(mv.z), "f"(mv.w) : "memory");
}

// ---------------------------------------------------------------------------
// fused MLP on HMMA (mma.sync bf16, 2-term split => ~fp32 accuracy)
// CTA: 256 threads (8 warps), 128 rows. Warp w owns rows [16w, 16w+16).
// smem: bf16 tiles [128][136] (8-col pad => conflict-free ldmatrix)
// ---------------------------------------------------------------------------
static constexpr int RS = 136;                      // row stride (bf16 elems)
static constexpr int SM_AHI = 0;
static constexpr int SM_ALO = SM_AHI + 128 * RS * 2;   // 34816
static constexpr int SM_WHI = SM_ALO + 128 * RS * 2;
static constexpr int SM_WLO = SM_WHI + 128 * RS * 2;
static constexpr int SM_B1  = SM_WLO + 128 * RS * 2;   // 139264
static constexpr int SM_B2  = SM_B1 + 512;
static constexpr int SM_TOTAL = SM_B2 + 512;           // 140288 B

// copy 128x128 bf16 global image into padded smem tile
__device__ __forceinline__ void copy_w(char* smem, int dst,
                                       const __nv_bfloat16* src, int tid) {
    const uint4* s = reinterpret_cast<const uint4*>(src);
    #pragma unroll
    for (int i = tid; i < 2048; i += 256) {
        int r = i >> 4, c8 = i & 15;
        *reinterpret_cast<uint4*>(smem + dst + (r * RS + c8 * 8) * 2) = s[i];
    }
}

// one GEMM layer: c[16][4] += split-GEMM( A(smem) , W(smem) )
__device__ __forceinline__ void gemm_layer(uint32_t sb, int wid, int lane,
                                           float c[16][4]) {
    int arow = wid * 16 + (lane & 15);
    int acolo = (lane & 16) ? 8 : 0;
    int brow_base = (lane & 7) + ((lane >= 16) ? 8 : 0);
    int bcolo = (lane & 8) ? 8 : 0;

    #pragma unroll
    for (int kk = 0; kk < 8; kk++) {
        int k0 = kk * 16;
        uint32_t aAddr = sb + SM_AHI + (uint32_t)(arow * RS + k0 + acolo) * 2;
        uint32_t ahi[4], alo[4];
        ldsm4(ahi, aAddr);
        ldsm4(alo, aAddr + (SM_ALO - SM_AHI));
        #pragma unroll
        for (int nt2 = 0; nt2 < 8; nt2++) {
            int nrow = nt2 * 16 + brow_base;
            uint32_t bAddr = sb + SM_WHI + (uint32_t)(nrow * RS + k0 + bcolo) * 2;
            uint32_t bhi[4], blo[4];
            ldsm4(bhi, bAddr);
            ldsm4(blo, bAddr + (SM_WLO - SM_WHI));
            mma16816(c[2 * nt2],     ahi, bhi[0], bhi[1]);
            mma16816(c[2 * nt2],     ahi, blo[0], blo[1]);
            mma16816(c[2 * nt2],     alo, bhi[0], bhi[1]);
            mma16816(c[2 * nt2 + 1], ahi, bhi[2], bhi[3]);
            mma16816(c[2 * nt2 + 1], ahi, blo[2], blo[3]);
            mma16816(c[2 * nt2 + 1], alo, bhi[2], bhi[3]);
        }
    }
}

__global__ void __launch_bounds__(256, 1)
mlp_kernel(const float* __restrict__ b1, const float* __restrict__ b2,
           float* __restrict__ out, int N) {
    extern __shared__ char smem[];
    uint32_t sb = smem_to_u32(smem);
    int tid = threadIdx.x;
    int wid = tid >> 5;
    int lane = tid & 31;
    int row0 = blockIdx.x * 128;

    // stage W1 + biases
    copy_w(smem, SM_WHI, g_w1hi, tid);
    copy_w(smem, SM_WLO, g_w1lo, tid);
    if (tid < 128) {
        reinterpret_cast<float*>(smem + SM_B1)[tid] = b1[tid];
        reinterpret_cast<float*>(smem + SM_B2)[tid] = b2[tid];
    }

    // stage A = g_acc rows (split hi/lo). thread -> (row, 64-col half)
    {
        int row = tid >> 1;
        int cb = (tid & 1) * 64;
        int gr = row0 + row;
        const float4* ar = reinterpret_cast<const float4*>(
            g_acc + (size_t)gr * D + cb);
        #pragma unroll
        for (int j = 0; j < 16; j++) {
            float4 v = (gr < N) ? ar[j] : make_float4(0.f, 0.f, 0.f, 0.f);
            uint32_t h0, l0, h1, l1;
            split2(v.x, v.y, h0, l0);
            split2(v.z, v.w, h1, l1);
            int boff = (row * RS + cb + 4 * j) * 2;
            *reinterpret_cast<uint2*>(smem + SM_AHI + boff) = make_uint2(h0, h1);
            *reinterpret_cast<uint2*>(smem + SM_ALO + boff) = make_uint2(l0, l1);
        }
    }
    __syncthreads();

    float c[16][4];
    #pragma unroll
    for (int i = 0; i < 16; i++)
        c[i][0] = c[i][1] = c[i][2] = c[i][3] = 0.f;

    // ---- layer 1 ----
    gemm_layer(sb, wid, lane, c);

    // epilogue 1: hidden = relu(c + b1) -> back into A smem (own rows only)
    {
        const float* b1s = reinterpret_cast<const float*>(smem + SM_B1);
        int row = wid * 16 + (lane >> 2);
        #pragma unroll
        for (int nt = 0; nt < 16; nt++) {
            int n = nt * 8 + (lane & 3) * 2;
            float bb0 = b1s[n], bb1 = b1s[n + 1];
            uint32_t hp, lp;
            split2(fmaxf(c[nt][0] + bb0, 0.f), fmaxf(c[nt][1] + bb1, 0.f), hp, lp);
            int boff = (row * RS + n) * 2;
            *reinterpret_cast<uint32_t*>(smem + SM_AHI + boff) = hp;
            *reinterpret_cast<uint32_t*>(smem + SM_ALO + boff) = lp;
            split2(fmaxf(c[nt][2] + bb0, 0.f), fmaxf(c[nt][3] + bb1, 0.f), hp, lp);
            boff = ((row + 8) * RS + n) * 2;
            *reinterpret_cast<uint32_t*>(smem + SM_AHI + boff) = hp;
            *reinterpret_cast<uint32_t*>(smem + SM_ALO + boff) = lp;
        }
    }
    __syncthreads();   // all W1 reads + hidden writes done

    // stage W2
    copy_w(smem, SM_WHI, g_w2hi, tid);
    copy_w(smem, SM_WLO, g_w2lo, tid);
    __syncthreads();

    #pragma unroll
    for (int i = 0; i < 16; i++)
        c[i][0] = c[i][1] = c[i][2] = c[i][3] = 0.f;

    // ---- layer 2 ----
    gemm_layer(sb, wid, lane, c);

    // epilogue 2: out = c + b2
    {
        const float* b2s = reinterpret_cast<const float*>(smem + SM_B2);
        int row = wid * 16 + (lane >> 2);
        int gr0 = row0 + row;
        #pragma unroll
        for (int nt = 0; nt < 16; nt++) {
            int n = nt * 8 + (lane & 3) * 2;
            float bb0 = b2s[n], bb1 = b2s[n + 1];
            if (gr0 < N)
                *reinterpret_cast<float2*>(out + (size_t)gr0 * D + n) =
                    make_float2(c[nt][0] + bb0, c[nt][1] + bb1);
            if (gr0 + 8 < N)
                *reinterpret_cast<float2*>(out + (size_t)(gr0 + 8) * D + n) =
                    make_float2(c[nt][2] + bb0, c[nt][3] + bb1);
        }
    }
}

// ---------------------------------------------------------------------------
// launch: init -> scatter -> prep -> HMMA MLP
// ---------------------------------------------------------------------------
extern "C" void kernel_launch(void* const* d_in, const int* in_sizes, int n_in,
                              void* d_out, int out_size) {
    const float* x   = (const float*)d_in[0];
    const float* ea  = (const float*)d_in[1];
    const float* W1  = (const float*)d_in[2];
    const float* b1  = (const float*)d_in[3];
    const float* W2  = (const float*)d_in[4];
    const float* b2  = (const float*)d_in[5];
    const float* eps = (const float*)d_in[6];
    const int*   ei  = (const int*)d_in[7];

    int N = in_sizes[0] / D;
    int E = in_sizes[1] / D;

    int n4 = N * D / 4;
    init_kernel<<<(n4 + 255) / 256, 256>>>(x, eps, n4);

    prep_kernel<<<128, 256>>>(W1, W2);

    long long scatter_threads = (long long)E * 32;
    scatter_kernel<<<(int)((scatter_threads + 255) / 256), 256>>>(x, ea, ei, E);

    cudaFuncSetAttribute(mlp_kernel,
                         cudaFuncAttributeMaxDynamicSharedMemorySize, SM_TOTAL);
    int nb = (N + 127) / 128;
    mlp_kernel<<<nb, 256, SM_TOTAL>>>(b1, b2, (float*)d_out, N);
}

// round 4
// speedup vs baseline: 1.5907x; 1.2067x over previous
#include <cuda_runtime.h>
#include <cuda_bf16.h>
#include <cstdint>

static constexpr int D = 128;       // feature dim == hidden dim
static constexpr int MAXN = 100000;

// accumulator: neighbor sums (zeroed by memset; (1+eps)*x folded into MLP)
__device__ float g_acc[(size_t)MAXN * D];
// pre-split, transposed bf16 weights: [n][k] row-major, 128x128 each
__device__ __align__(16) __nv_bfloat16 g_w1hi[16384];
__device__ __align__(16) __nv_bfloat16 g_w1lo[16384];
__device__ __align__(16) __nv_bfloat16 g_w2hi[16384];
__device__ __align__(16) __nv_bfloat16 g_w2lo[16384];

// ---------------------------------------------------------------------------
// helpers
// ---------------------------------------------------------------------------
__device__ __forceinline__ uint32_t smem_to_u32(const void* p) {
    uint32_t a;
    asm("{ .reg .u64 t; cvta.to.shared.u64 t, %1; cvt.u32.u64 %0, t; }"
        : "=r"(a) : "l"(p));
    return a;
}
__device__ __forceinline__ void ldsm4(uint32_t r[4], uint32_t addr) {
    asm volatile("ldmatrix.sync.aligned.m8n8.x4.shared.b16 {%0,%1,%2,%3}, [%4];"
                 : "=r"(r[0]), "=r"(r[1]), "=r"(r[2]), "=r"(r[3]) : "r"(addr));
}
__device__ __forceinline__ void mma16816(float c[4], const uint32_t a[4],
                                         uint32_t b0, uint32_t b1) {
    asm volatile("mma.sync.aligned.m16n8k16.row.col.f32.bf16.bf16.f32 "
                 "{%0,%1,%2,%3}, {%4,%5,%6,%7}, {%8,%9}, {%0,%1,%2,%3};"
                 : "+f"(c[0]), "+f"(c[1]), "+f"(c[2]), "+f"(c[3])
                 : "r"(a[0]), "r"(a[1]), "r"(a[2]), "r"(a[3]),
                   "r"(b0), "r"(b1));
}
// split two floats into packed bf16x2 hi + lo words
__device__ __forceinline__ void split2(float v0, float v1,
                                       uint32_t& hp, uint32_t& lp) {
    __nv_bfloat16 h0 = __float2bfloat16(v0);
    __nv_bfloat16 h1 = __float2bfloat16(v1);
    __nv_bfloat16 l0 = __float2bfloat16(v0 - __bfloat162float(h0));
    __nv_bfloat16 l1 = __float2bfloat16(v1 - __bfloat162float(h1));
    hp = (uint32_t)__bfloat16_as_ushort(h0) |
         ((uint32_t)__bfloat16_as_ushort(h1) << 16);
    lp = (uint32_t)__bfloat16_as_ushort(l0) |
         ((uint32_t)__bfloat16_as_ushort(l1) << 16);
}

// ---------------------------------------------------------------------------
// weight prep: W [k][n] f32 -> hi/lo bf16 at [n][k]
// ---------------------------------------------------------------------------
__global__ void prep_kernel(const float* __restrict__ W1,
                            const float* __restrict__ W2) {
    int idx = blockIdx.x * blockDim.x + threadIdx.x;  // 0..32767
    int m = idx >> 14;
    int r = idx & 16383;
    int k = r >> 7, n = r & 127;
    float w = (m ? W2 : W1)[k * 128 + n];
    __nv_bfloat16 h = __float2bfloat16(w);
    __nv_bfloat16 l = __float2bfloat16(w - __bfloat162float(h));
    int e = n * 128 + k;
    if (m) { g_w2hi[e] = h; g_w2lo[e] = l; }
    else   { g_w1hi[e] = h; g_w1lo[e] = l; }
}

// ---------------------------------------------------------------------------
// scatter: one warp per edge, red.global.add.v4.f32
// ---------------------------------------------------------------------------
__global__ void scatter_kernel(const float* __restrict__ x,
                               const float* __restrict__ ea,
                               const int* __restrict__ ei, int E) {
    int gtid = blockIdx.x * blockDim.x + threadIdx.x;
    int e = gtid >> 5;
    int lane = gtid & 31;
    if (e >= E) return;

    int u = ei[e];
    int v = ei[E + e];

    float4 a  = __ldcs(reinterpret_cast<const float4*>(ea + (size_t)e * D) + lane);
    float4 xu = reinterpret_cast<const float4*>(x + (size_t)u * D)[lane];
    float4 xv = reinterpret_cast<const float4*>(x + (size_t)v * D)[lane];

    float4 mu, mv;
    mu.x = fmaxf(xv.x + a.x, 0.0f); mu.y = fmaxf(xv.y + a.y, 0.0f);
    mu.z = fmaxf(xv.z + a.z, 0.0f); mu.w = fmaxf(xv.w + a.w, 0.0f);
    mv.x = fmaxf(xu.x + a.x, 0.0f); mv.y = fmaxf(xu.y + a.y, 0.0f);
    mv.z = fmaxf(xu.z + a.z, 0.0f); mv.w = fmaxf(xu.w + a.w, 0.0f);

    float* pu = g_acc + (size_t)u * D + lane * 4;
    float* pv = g_acc + (size_t)v * D + lane * 4;
    asm volatile("red.global.add.v4.f32 [%0], {%1,%2,%3,%4};"
                 :: "l"(pu), "f"(mu.x), "f"(mu.y), "f"(mu.z), "f"(mu.w) : "memory");
    asm volatile("red.global.add.v4.f32 [%0], {%1,%2,%3,%4};"
                 :: "l"(pv), "f"(mv.x), "f"(mv.y), "f"(mv.z), "f"(mv.w) : "memory");
}

// ---------------------------------------------------------------------------
// fused MLP on HMMA (bf16 2-term split => ~fp32 accuracy)
// CTA: 256 threads / 8 warps / 128 rows; warp owns rows [16w,16w+16).
// A fragments built directly from gmem (no A smem, no ldmatrix for A).
// Hidden kept in registers (accum frag == layer-2 A frag layout).
// smem: W hi/lo [128][136] only => 2 CTAs/SM.
// ---------------------------------------------------------------------------
static constexpr int RS = 136;                       // row stride (bf16)
static constexpr int SM_WHI = 0;
static constexpr int SM_WLO = SM_WHI + 128 * RS * 2; // 34816
static constexpr int SM_B1  = SM_WLO + 128 * RS * 2; // 69632
static constexpr int SM_B2  = SM_B1 + 512;
static constexpr int SM_TOTAL = SM_B2 + 512;         // 70656 B

__device__ __forceinline__ void copy_w(char* smem, int dst,
                                       const __nv_bfloat16* src, int tid) {
    const uint4* s = reinterpret_cast<const uint4*>(src);
    #pragma unroll
    for (int i = tid; i < 2048; i += 256) {
        int r = i >> 4, c8 = i & 15;
        *reinterpret_cast<uint4*>(smem + dst + (r * RS + c8 * 8) * 2) = s[i];
    }
}

// build one A-frag reg pair (hi, lo) from gmem row at col k (float2), scaled
__device__ __forceinline__ void load_split(const float* ap, const float* xp,
                                           bool valid, int k, float s,
                                           uint32_t& hp, uint32_t& lp) {
    float v0 = 0.f, v1 = 0.f;
    if (valid) {
        float2 pa = *reinterpret_cast<const float2*>(ap + k);
        float2 px = *reinterpret_cast<const float2*>(xp + k);
        v0 = fmaf(s, px.x, pa.x);
        v1 = fmaf(s, px.y, pa.y);
    }
    split2(v0, v1, hp, lp);
}

__global__ void __launch_bounds__(256, 2)
mlp_kernel(const float* __restrict__ x, const float* __restrict__ eps,
           const float* __restrict__ b1, const float* __restrict__ b2,
           float* __restrict__ out, int N) {
    extern __shared__ char smem[];
    uint32_t sb = smem_to_u32(smem);
    int tid = threadIdx.x;
    int wid = tid >> 5;
    int lane = tid & 31;
    int row0 = blockIdx.x * 128;

    copy_w(smem, SM_WHI, g_w1hi, tid);
    copy_w(smem, SM_WLO, g_w1lo, tid);
    if (tid < 128) {
        reinterpret_cast<float*>(smem + SM_B1)[tid] = b1[tid];
        reinterpret_cast<float*>(smem + SM_B2)[tid] = b2[tid];
    }
    __syncthreads();

    int m2 = (lane & 3) * 2;
    int g  = lane >> 2;
    int r0 = row0 + wid * 16 + g;
    int r1 = r0 + 8;
    bool val0 = r0 < N, val1 = r1 < N;
    const float* a0p = g_acc + (size_t)r0 * D;
    const float* a1p = g_acc + (size_t)r1 * D;
    const float* x0p = x + (size_t)r0 * D;
    const float* x1p = x + (size_t)r1 * D;
    float s = 1.0f + eps[0];

    int brow = (lane & 7) + ((lane & 16) ? 8 : 0);
    int bcol = (lane & 8) ? 8 : 0;

    float c1[16][4];
    #pragma unroll
    for (int i = 0; i < 16; i++)
        c1[i][0] = c1[i][1] = c1[i][2] = c1[i][3] = 0.f;

    // ---- layer 1: A from gmem, W1 from smem ----
    #pragma unroll 2
    for (int kk = 0; kk < 8; kk++) {
        int k0 = kk * 16 + m2;
        uint32_t ahi[4], alo[4];
        load_split(a0p, x0p, val0, k0,     s, ahi[0], alo[0]);
        load_split(a1p, x1p, val1, k0,     s, ahi[1], alo[1]);
        load_split(a0p, x0p, val0, k0 + 8, s, ahi[2], alo[2]);
        load_split(a1p, x1p, val1, k0 + 8, s, ahi[3], alo[3]);
        #pragma unroll
        for (int nt2 = 0; nt2 < 8; nt2++) {
            uint32_t bAddr = sb + SM_WHI +
                (uint32_t)((nt2 * 16 + brow) * RS + kk * 16 + bcol) * 2;
            uint32_t bhi[4], blo[4];
            ldsm4(bhi, bAddr);
            ldsm4(blo, bAddr + (SM_WLO - SM_WHI));
            mma16816(c1[2 * nt2],     ahi, bhi[0], bhi[1]);
            mma16816(c1[2 * nt2],     ahi, blo[0], blo[1]);
            mma16816(c1[2 * nt2],     alo, bhi[0], bhi[1]);
            mma16816(c1[2 * nt2 + 1], ahi, bhi[2], bhi[3]);
            mma16816(c1[2 * nt2 + 1], ahi, blo[2], blo[3]);
            mma16816(c1[2 * nt2 + 1], alo, bhi[2], bhi[3]);
        }
    }

    // ---- hidden = relu(c1 + b1), re-fragmented in registers ----
    // accum frag of ntiles (2j,2j+1) == layer-2 A frag for k-chunk j
    const float* b1s = reinterpret_cast<const float*>(smem + SM_B1);
    uint32_t hh[8][4], hl[8][4];
    #pragma unroll
    for (int j = 0; j < 8; j++) {
        float be0 = b1s[16 * j + m2],     be1 = b1s[16 * j + m2 + 1];
        float bo0 = b1s[16 * j + 8 + m2], bo1 = b1s[16 * j + 8 + m2 + 1];
        split2(fmaxf(c1[2 * j][0] + be0, 0.f),
               fmaxf(c1[2 * j][1] + be1, 0.f), hh[j][0], hl[j][0]);
        split2(fmaxf(c1[2 * j][2] + be0, 0.f),
               fmaxf(c1[2 * j][3] + be1, 0.f), hh[j][1], hl[j][1]);
        split2(fmaxf(c1[2 * j + 1][0] + bo0, 0.f),
               fmaxf(c1[2 * j + 1][1] + bo1, 0.f), hh[j][2], hl[j][2]);
        split2(fmaxf(c1[2 * j + 1][2] + bo0, 0.f),
               fmaxf(c1[2 * j + 1][3] + bo1, 0.f), hh[j][3], hl[j][3]);
    }

    __syncthreads();               // everyone done reading W1
    copy_w(smem, SM_WHI, g_w2hi, tid);
    copy_w(smem, SM_WLO, g_w2lo, tid);
    __syncthreads();

    // ---- layer 2 in two n-halves (c2 = 32 regs) ----
    const float* b2s = reinterpret_cast<const float*>(smem + SM_B2);
    #pragma unroll
    for (int h = 0; h < 2; h++) {
        float c2[8][4];
        #pragma unroll
        for (int i = 0; i < 8; i++)
            c2[i][0] = c2[i][1] = c2[i][2] = c2[i][3] = 0.f;

        #pragma unroll
        for (int kk = 0; kk < 8; kk++) {
            #pragma unroll
            for (int i = 0; i < 4; i++) {
                int nt2 = h * 4 + i;
                uint32_t bAddr = sb + SM_WHI +
                    (uint32_t)((nt2 * 16 + brow) * RS + kk * 16 + bcol) * 2;
                uint32_t bhi[4], blo[4];
                ldsm4(bhi, bAddr);
                ldsm4(blo, bAddr + (SM_WLO - SM_WHI));
                mma16816(c2[2 * i],     hh[kk], bhi[0], bhi[1]);
                mma16816(c2[2 * i],     hh[kk], blo[0], blo[1]);
                mma16816(c2[2 * i],     hl[kk], bhi[0], bhi[1]);
                mma16816(c2[2 * i + 1], hh[kk], bhi[2], bhi[3]);
                mma16816(c2[2 * i + 1], hh[kk], blo[2], blo[3]);
                mma16816(c2[2 * i + 1], hl[kk], bhi[2], bhi[3]);
            }
        }

        #pragma unroll
        for (int nt = 0; nt < 8; nt++) {
            int col = (h * 8 + nt) * 8 + m2;
            float bb0 = b2s[col], bb1 = b2s[col + 1];
            if (val0)
                *reinterpret_cast<float2*>(out + (size_t)r0 * D + col) =
                    make_float2(c2[nt][0] + bb0, c2[nt][1] + bb1);
            if (val1)
                *reinterpret_cast<float2*>(out + (size_t)r1 * D + col) =
                    make_float2(c2[nt][2] + bb0, c2[nt][3] + bb1);
        }
    }
}

// ---------------------------------------------------------------------------
// launch: memset acc -> prep -> scatter -> HMMA MLP
// ---------------------------------------------------------------------------
extern "C" void kernel_launch(void* const* d_in, const int* in_sizes, int n_in,
                              void* d_out, int out_size) {
    const float* x   = (const float*)d_in[0];
    const float* ea  = (const float*)d_in[1];
    const float* W1  = (const float*)d_in[2];
    const float* b1  = (const float*)d_in[3];
    const float* W2  = (const float*)d_in[4];
    const float* b2  = (const float*)d_in[5];
    const float* eps = (const float*)d_in[6];
    const int*   ei  = (const int*)d_in[7];

    int N = in_sizes[0] / D;
    int E = in_sizes[1] / D;

    void* accp = nullptr;
    cudaGetSymbolAddress(&accp, g_acc);
    cudaMemsetAsync(accp, 0, (size_t)N * D * sizeof(float));

    prep_kernel<<<128, 256>>>(W1, W2);

    long long scatter_threads = (long long)E * 32;
    scatter_kernel<<<(int)((scatter_threads + 255) / 256), 256>>>(x, ea, ei, E);

    cudaFuncSetAttribute(mlp_kernel,
                         cudaFuncAttributeMaxDynamicSharedMemorySize, SM_TOTAL);
    int nb = (N + 127) / 128;
    mlp_kernel<<<nb, 256, SM_TOTAL>>>(x, eps, b1, b2, (float*)d_out, N);
}